// round 1
// baseline (speedup 1.0000x reference)
#include <cuda_runtime.h>
#include <math.h>

#define L    128
#define NB   64
#define DD   768
#define IN   64
#define OUTD 64
#define NO   32
#define EPSV 1e-8f

// ---------------- scratch (device globals; no allocation allowed) ----------
__device__ float g_mu_in[L * NB * IN];          // (l, n, i)     2 MB
__device__ float g_fa[L * NB];                  // (l, n)
__device__ float g_V[(size_t)L * NO * NB * OUTD]; // (l, o, n, j) 64 MB
__device__ float g_R[NO * NB * L];              // (o, n, l)     1 MB
__device__ float g_mu[NO * NB * OUTD];          // (o, n, j)
__device__ float g_i2v[NO * NB * OUTD];         // 1/(2 var + eps)
__device__ float g_C[NO * NB];                  // logsig(a) - 1 - pi/2 - 0.5*sum log(var+eps)

// ---------------- kernel 1: a_in + mu_in ------------------------------------
// grid = L, block = 256. Computes mu_in[l] = gelu(x_t[l] @ Wcap[l] + Bcap[l])
// (64x64 output, K=768) and f_a[l,n] = sigmoid(x_t[l] @ Wscore[l] + Bscore[l]).
__global__ __launch_bounds__(256) void front_kernel(
    const float* __restrict__ x,      // (N, L, D)
    const float* __restrict__ Wsc,    // (L, D)
    const float* __restrict__ Bsc,    // (L)
    const float* __restrict__ Wc,     // (L, D, IN)
    const float* __restrict__ Bc)     // (L, IN)
{
    __shared__ float As[64][33];                      // (n, k) padded
    __shared__ __align__(16) float Bs[32][64];        // (k, i) float4-readable

    const int l   = blockIdx.x;
    const int tid = threadIdx.x;
    const int tn  = tid >> 4;   // 0..15
    const int tj  = tid & 15;   // 0..15

    float acc[4][4] = {};

    for (int kk = 0; kk < DD; kk += 32) {
        #pragma unroll
        for (int p = 0; p < 8; p++) {
            int e = tid + p * 256;
            int n = e >> 5, k = e & 31;
            As[n][k] = x[((size_t)n * L + l) * DD + kk + k];
        }
        #pragma unroll
        for (int p = 0; p < 8; p++) {
            int e = tid + p * 256;
            int k = e >> 6, i = e & 63;
            Bs[k][i] = Wc[(size_t)l * DD * IN + (size_t)(kk + k) * IN + i];
        }
        __syncthreads();
        #pragma unroll
        for (int k = 0; k < 32; k++) {
            float a0 = As[tn * 4 + 0][k];
            float a1 = As[tn * 4 + 1][k];
            float a2 = As[tn * 4 + 2][k];
            float a3 = As[tn * 4 + 3][k];
            float4 b = reinterpret_cast<const float4*>(&Bs[k][0])[tj];
            acc[0][0] += a0 * b.x; acc[0][1] += a0 * b.y; acc[0][2] += a0 * b.z; acc[0][3] += a0 * b.w;
            acc[1][0] += a1 * b.x; acc[1][1] += a1 * b.y; acc[1][2] += a1 * b.z; acc[1][3] += a1 * b.w;
            acc[2][0] += a2 * b.x; acc[2][1] += a2 * b.y; acc[2][2] += a2 * b.z; acc[2][3] += a2 * b.w;
            acc[3][0] += a3 * b.x; acc[3][1] += a3 * b.y; acc[3][2] += a3 * b.z; acc[3][3] += a3 * b.w;
        }
        __syncthreads();
    }

    // bias + exact gelu, write mu_in
    #pragma unroll
    for (int r = 0; r < 4; r++) {
        int n = tn * 4 + r;
        #pragma unroll
        for (int c = 0; c < 4; c++) {
            int i = tj * 4 + c;
            float v = acc[r][c] + Bc[l * IN + i];
            g_mu_in[(size_t)l * NB * IN + (size_t)n * IN + i] = v * normcdff(v);
        }
    }

    // a_in / f_a: warp w handles n = w, w+8, ...
    const int w = tid >> 5, lane = tid & 31;
    for (int n = w; n < NB; n += 8) {
        float s = 0.f;
        const float* xr = x + ((size_t)n * L + l) * DD;
        const float* wr = Wsc + (size_t)l * DD;
        for (int d = lane; d < DD; d += 32) s += xr[d] * wr[d];
        #pragma unroll
        for (int off = 16; off; off >>= 1) s += __shfl_down_sync(0xffffffffu, s, off);
        if (lane == 0) {
            float a = s + Bsc[l];
            g_fa[l * NB + n] = 1.f / (1.f + expf(-a));
        }
    }
}

// ---------------- kernel 2: votes V ------------------------------------------
// grid = L*NO, block = 256. V[l,o] = mu_in[l] (64x64) @ Wvote[l,o] (64x64) + Bvote[l,o]
__global__ __launch_bounds__(256) void vote_kernel(
    const float* __restrict__ Wv,    // (L, NO, IN, OUT)
    const float* __restrict__ Bv)    // (L, NO, OUT)
{
    __shared__ float As[64][65];                   // (n, i) padded
    __shared__ __align__(16) float Bs[64][64];     // (i, j)

    const int lo  = blockIdx.x;   // l*32 + o
    const int l   = lo >> 5;
    const int tid = threadIdx.x;

    const float* A = g_mu_in + (size_t)l * NB * IN;
    const float* B = Wv + (size_t)lo * IN * OUTD;

    #pragma unroll
    for (int p = 0; p < 16; p++) {
        int e = tid + p * 256;
        As[e >> 6][e & 63] = A[e];
        Bs[e >> 6][e & 63] = B[e];
    }
    __syncthreads();

    const int tn = tid >> 4, tj = tid & 15;
    float acc[4][4] = {};
    #pragma unroll
    for (int i = 0; i < 64; i++) {
        float a0 = As[tn * 4 + 0][i];
        float a1 = As[tn * 4 + 1][i];
        float a2 = As[tn * 4 + 2][i];
        float a3 = As[tn * 4 + 3][i];
        float4 b = reinterpret_cast<const float4*>(&Bs[i][0])[tj];
        acc[0][0] += a0 * b.x; acc[0][1] += a0 * b.y; acc[0][2] += a0 * b.z; acc[0][3] += a0 * b.w;
        acc[1][0] += a1 * b.x; acc[1][1] += a1 * b.y; acc[1][2] += a1 * b.z; acc[1][3] += a1 * b.w;
        acc[2][0] += a2 * b.x; acc[2][1] += a2 * b.y; acc[2][2] += a2 * b.z; acc[2][3] += a2 * b.w;
        acc[3][0] += a3 * b.x; acc[3][1] += a3 * b.y; acc[3][2] += a3 * b.z; acc[3][3] += a3 * b.w;
    }

    float4 bias = reinterpret_cast<const float4*>(Bv + (size_t)lo * OUTD)[tj];
    float* Vout = g_V + (size_t)lo * NB * OUTD;
    #pragma unroll
    for (int r = 0; r < 4; r++) {
        float4 o4;
        o4.x = acc[r][0] + bias.x;
        o4.y = acc[r][1] + bias.y;
        o4.z = acc[r][2] + bias.z;
        o4.w = acc[r][3] + bias.w;
        reinterpret_cast<float4*>(Vout + (size_t)(tn * 4 + r) * OUTD)[tj] = o4;
    }
}

// ---------------- kernel 3: EM step -----------------------------------------
// grid = NO*NB (bid = o*64 + n), block = 64 (thread = j).
__global__ __launch_bounds__(64) void em_kernel(
    const float* __restrict__ bu,   // beta_use (L)
    const float* __restrict__ bi,   // beta_ign (NO)
    int uniform, int write_out, float* __restrict__ out)
{
    const int bid = blockIdx.x;
    const int o = bid >> 6, n = bid & 63;
    const int j = threadIdx.x;

    float s0 = 0.f, s1 = 0.f, s2 = 0.f, sbu = 0.f, sfa = 0.f;
    const float* Rp = g_R + (size_t)bid * L;

    #pragma unroll 4
    for (int l = 0; l < L; l++) {
        float fa = g_fa[l * NB + n];
        float Dv = uniform ? fa * (1.f / 32.f) : fa * Rp[l];
        float v  = g_V[(((size_t)l * NO + o) * NB + n) * OUTD + j];
        s0 += Dv;
        s1 += Dv * v;
        s2 += Dv * v * v;
        sbu += bu[l] * Dv;
        sfa += fa;
    }

    float denom = s0 + EPSV;
    float m   = s1 / denom;
    float var = (s2 - 2.f * m * s1 + m * m * s0) / denom;
    var = fmaxf(var, 0.f);
    float a = sbu - bi[o] * (sfa - s0);

    g_mu[(size_t)bid * OUTD + j]  = m;
    g_i2v[(size_t)bid * OUTD + j] = 1.f / (2.f * var + EPSV);

    float lv = logf(var + EPSV);
    __shared__ float red[2];
    #pragma unroll
    for (int off = 16; off; off >>= 1) lv += __shfl_down_sync(0xffffffffu, lv, off);
    if ((j & 31) == 0) red[j >> 5] = lv;
    __syncthreads();
    if (j == 0) {
        float slv = red[0] + red[1];
        float lsig = (a > 0.f) ? -log1pf(expf(-a)) : a - log1pf(expf(a));
        g_C[bid] = lsig - 1.f - 0.5f * 3.14159265358979323846f - 0.5f * slv;
    }

    if (write_out) {
        if (j == 0) out[n * NO + o] = a;                       // a_out (N, NO)
        out[NB * NO + ((size_t)n * NO + o) * OUTD + j] = m;    // mu_out (N, NO, OUT)
    }
}

// ---------------- kernel 4: routing (R update) -------------------------------
// grid = L*NB (bid = l*64 + n), block = 256 (8 warps).
__global__ __launch_bounds__(256) void route_kernel()
{
    const int bid = blockIdx.x;
    const int l = bid >> 6, n = bid & 63;
    const int w = threadIdx.x >> 5, lane = threadIdx.x & 31;

    __shared__ float logit[NO];

    #pragma unroll
    for (int s = 0; s < 4; s++) {
        int o = w + s * 8;
        const float* Vp = g_V + (((size_t)l * NO + o) * NB + n) * OUTD;
        const float* mp = g_mu + ((size_t)o * NB + n) * OUTD;
        const float* ip = g_i2v + ((size_t)o * NB + n) * OUTD;
        float d0 = Vp[lane]      - mp[lane];
        float d1 = Vp[lane + 32] - mp[lane + 32];
        float acc = d0 * d0 * ip[lane] + d1 * d1 * ip[lane + 32];
        #pragma unroll
        for (int off = 16; off; off >>= 1) acc += __shfl_down_sync(0xffffffffu, acc, off);
        if (lane == 0) logit[o] = g_C[o * NB + n] - acc;
    }
    __syncthreads();

    if (w == 0) {
        float v = logit[lane];
        float m = v;
        #pragma unroll
        for (int off = 16; off; off >>= 1) m = fmaxf(m, __shfl_xor_sync(0xffffffffu, m, off));
        float e = expf(v - m);
        float ss = e;
        #pragma unroll
        for (int off = 16; off; off >>= 1) ss += __shfl_xor_sync(0xffffffffu, ss, off);
        g_R[((size_t)lane * NB + n) * L + l] = e / ss;   // R layout (o, n, l)
    }
}

// ---------------- launch ------------------------------------------------------
extern "C" void kernel_launch(void* const* d_in, const int* in_sizes, int n_in,
                              void* d_out, int out_size)
{
    const float* x      = (const float*)d_in[0];
    const float* Wscore = (const float*)d_in[1];
    const float* Bscore = (const float*)d_in[2];
    const float* Wcap   = (const float*)d_in[3];
    const float* Bcap   = (const float*)d_in[4];
    const float* Wvote  = (const float*)d_in[5];
    const float* Bvote  = (const float*)d_in[6];
    const float* bu     = (const float*)d_in[7];
    const float* bi     = (const float*)d_in[8];
    float* out = (float*)d_out;

    front_kernel<<<L, 256>>>(x, Wscore, Bscore, Wcap, Bcap);
    vote_kernel<<<L * NO, 256>>>(Wvote, Bvote);

    // iters = 3 (fixed by setup_inputs): E(uniform), R, E, R, E(write_out)
    em_kernel<<<NO * NB, 64>>>(bu, bi, 1, 0, out);
    route_kernel<<<L * NB, 256>>>();
    em_kernel<<<NO * NB, 64>>>(bu, bi, 0, 0, out);
    route_kernel<<<L * NB, 256>>>();
    em_kernel<<<NO * NB, 64>>>(bu, bi, 0, 1, out);
}

// round 2
// speedup vs baseline: 1.1700x; 1.1700x over previous
#include <cuda_runtime.h>
#include <math.h>

#define L    128
#define NB   64
#define DD   768
#define IN   64
#define OUTD 64
#define NO   32
#define EPSV 1e-8f

// ---------------- scratch (device globals; no allocation allowed) ----------
__device__ float g_mu_in[L * NB * IN];            // (l, n, i)     2 MB
__device__ float g_fa[L * NB];                    // (l, n)
__device__ float g_V[(size_t)L * NO * NB * OUTD]; // (l, o, n, j)  64 MB (fits L2!)
__device__ float g_R[NO * NB * L];                // (o, n, l)     1 MB
__device__ float g_mu[NO * NB * OUTD];            // (o, n, j)
__device__ float g_i2v[NO * NB * OUTD];           // 1/(2 var + eps)
__device__ float g_C[NO * NB];                    // logsig(a) - 1 - pi/2 - 0.5*sum log(var+eps)

// ---------------- kernel 1: a_in + mu_in ------------------------------------
// grid = L, block = 256.
__global__ __launch_bounds__(256) void front_kernel(
    const float* __restrict__ x,      // (N, L, D)
    const float* __restrict__ Wsc,    // (L, D)
    const float* __restrict__ Bsc,    // (L)
    const float* __restrict__ Wc,     // (L, D, IN)
    const float* __restrict__ Bc)     // (L, IN)
{
    __shared__ float As[64][33];                      // (n, k) padded
    __shared__ __align__(16) float Bs[32][64];        // (k, i)

    const int l   = blockIdx.x;
    const int tid = threadIdx.x;
    const int tn  = tid >> 4;   // 0..15
    const int tj  = tid & 15;   // 0..15

    float acc[4][4] = {};

    for (int kk = 0; kk < DD; kk += 32) {
        #pragma unroll
        for (int p = 0; p < 8; p++) {
            int e = tid + p * 256;
            int n = e >> 5, k = e & 31;
            As[n][k] = __ldcs(&x[((size_t)n * L + l) * DD + kk + k]);
        }
        #pragma unroll
        for (int p = 0; p < 8; p++) {
            int e = tid + p * 256;
            int k = e >> 6, i = e & 63;
            Bs[k][i] = __ldcs(&Wc[(size_t)l * DD * IN + (size_t)(kk + k) * IN + i]);
        }
        __syncthreads();
        #pragma unroll
        for (int k = 0; k < 32; k++) {
            float a0 = As[tn * 4 + 0][k];
            float a1 = As[tn * 4 + 1][k];
            float a2 = As[tn * 4 + 2][k];
            float a3 = As[tn * 4 + 3][k];
            float4 b = reinterpret_cast<const float4*>(&Bs[k][0])[tj];
            acc[0][0] += a0 * b.x; acc[0][1] += a0 * b.y; acc[0][2] += a0 * b.z; acc[0][3] += a0 * b.w;
            acc[1][0] += a1 * b.x; acc[1][1] += a1 * b.y; acc[1][2] += a1 * b.z; acc[1][3] += a1 * b.w;
            acc[2][0] += a2 * b.x; acc[2][1] += a2 * b.y; acc[2][2] += a2 * b.z; acc[2][3] += a2 * b.w;
            acc[3][0] += a3 * b.x; acc[3][1] += a3 * b.y; acc[3][2] += a3 * b.z; acc[3][3] += a3 * b.w;
        }
        __syncthreads();
    }

    #pragma unroll
    for (int r = 0; r < 4; r++) {
        int n = tn * 4 + r;
        #pragma unroll
        for (int c = 0; c < 4; c++) {
            int i = tj * 4 + c;
            float v = acc[r][c] + Bc[l * IN + i];
            g_mu_in[(size_t)l * NB * IN + (size_t)n * IN + i] = v * normcdff(v);
        }
    }

    const int w = tid >> 5, lane = tid & 31;
    for (int n = w; n < NB; n += 8) {
        float s = 0.f;
        const float* xr = x + ((size_t)n * L + l) * DD;
        const float* wr = Wsc + (size_t)l * DD;
        for (int d = lane; d < DD; d += 32) s += xr[d] * wr[d];
        #pragma unroll
        for (int off = 16; off; off >>= 1) s += __shfl_down_sync(0xffffffffu, s, off);
        if (lane == 0) {
            float a = s + Bsc[l];
            g_fa[l * NB + n] = 1.f / (1.f + expf(-a));
        }
    }
}

// ---------------- kernel 2: votes V ------------------------------------------
// grid = L*NO, block = 256. Wvote read with evict-first so V stays in L2.
__global__ __launch_bounds__(256) void vote_kernel(
    const float* __restrict__ Wv,    // (L, NO, IN, OUT)
    const float* __restrict__ Bv)    // (L, NO, OUT)
{
    __shared__ float As[64][65];                   // (n, i) padded
    __shared__ __align__(16) float Bs[64][64];     // (i, j)

    const int lo  = blockIdx.x;   // l*32 + o
    const int l   = lo >> 5;
    const int tid = threadIdx.x;

    const float* A = g_mu_in + (size_t)l * NB * IN;
    const float* B = Wv + (size_t)lo * IN * OUTD;

    #pragma unroll
    for (int p = 0; p < 16; p++) {
        int e = tid + p * 256;
        As[e >> 6][e & 63] = A[e];
        Bs[e >> 6][e & 63] = __ldcs(&B[e]);     // streaming: don't evict V from L2
    }
    __syncthreads();

    const int tn = tid >> 4, tj = tid & 15;
    float acc[4][4] = {};
    #pragma unroll
    for (int i = 0; i < 64; i++) {
        float a0 = As[tn * 4 + 0][i];
        float a1 = As[tn * 4 + 1][i];
        float a2 = As[tn * 4 + 2][i];
        float a3 = As[tn * 4 + 3][i];
        float4 b = reinterpret_cast<const float4*>(&Bs[i][0])[tj];
        acc[0][0] += a0 * b.x; acc[0][1] += a0 * b.y; acc[0][2] += a0 * b.z; acc[0][3] += a0 * b.w;
        acc[1][0] += a1 * b.x; acc[1][1] += a1 * b.y; acc[1][2] += a1 * b.z; acc[1][3] += a1 * b.w;
        acc[2][0] += a2 * b.x; acc[2][1] += a2 * b.y; acc[2][2] += a2 * b.z; acc[2][3] += a2 * b.w;
        acc[3][0] += a3 * b.x; acc[3][1] += a3 * b.y; acc[3][2] += a3 * b.z; acc[3][3] += a3 * b.w;
    }

    float bx = __ldcs(&Bv[(size_t)lo * OUTD + tj * 4 + 0]);
    float by = __ldcs(&Bv[(size_t)lo * OUTD + tj * 4 + 1]);
    float bz = __ldcs(&Bv[(size_t)lo * OUTD + tj * 4 + 2]);
    float bw = __ldcs(&Bv[(size_t)lo * OUTD + tj * 4 + 3]);
    float* Vout = g_V + (size_t)lo * NB * OUTD;
    #pragma unroll
    for (int r = 0; r < 4; r++) {
        float4 o4;
        o4.x = acc[r][0] + bx;
        o4.y = acc[r][1] + by;
        o4.z = acc[r][2] + bz;
        o4.w = acc[r][3] + bw;
        reinterpret_cast<float4*>(Vout + (size_t)(tn * 4 + r) * OUTD)[tj] = o4;
    }
}

// ---------------- kernel 3: EM step -----------------------------------------
// grid = NO*NB (bid = o*64 + n), block = 64 = 2 warps. Warp w covers l in
// [w*64, w*64+64); lane handles j = {2*lane, 2*lane+1} via float2.
__global__ __launch_bounds__(64) void em_kernel(
    const float* __restrict__ bu,   // beta_use (L)
    const float* __restrict__ bi,   // beta_ign (NO)
    int uniform, int write_out, float* __restrict__ out)
{
    const int bid = blockIdx.x;
    const int o = bid >> 6, n = bid & 63;
    const int w = threadIdx.x >> 5, lane = threadIdx.x & 31;

    float2 s1 = {0.f, 0.f}, s2 = {0.f, 0.f};
    float s0 = 0.f, sbu = 0.f, sfa = 0.f;
    const float* Rp = g_R + (size_t)bid * L;
    const float2* V2 = reinterpret_cast<const float2*>(g_V);

    const int l0 = w * 64;
    #pragma unroll 4
    for (int li = 0; li < 64; li++) {
        int l = l0 + li;
        float fa = g_fa[l * NB + n];
        float Dv = uniform ? fa * (1.f / 32.f) : fa * Rp[l];
        float2 v = V2[(((size_t)l * NO + o) * NB + n) * 32 + lane];
        s0 += Dv;
        s1.x += Dv * v.x;       s1.y += Dv * v.y;
        s2.x += Dv * v.x * v.x; s2.y += Dv * v.y * v.y;
        sbu += bu[l] * Dv;
        sfa += fa;
    }

    // combine the two warps (lane j-mapping identical between warps)
    __shared__ float2 sh1[32], sh2[32];
    __shared__ float sh0, shbu, shfa;
    if (w == 1) {
        sh1[lane] = s1; sh2[lane] = s2;
        if (lane == 0) { sh0 = s0; shbu = sbu; shfa = sfa; }
    }
    __syncthreads();
    if (w == 0) {
        s1.x += sh1[lane].x; s1.y += sh1[lane].y;
        s2.x += sh2[lane].x; s2.y += sh2[lane].y;
        s0 += sh0; sbu += shbu; sfa += shfa;

        float denom = s0 + EPSV;
        float mx = s1.x / denom, my = s1.y / denom;
        float vx = fmaxf((s2.x - 2.f * mx * s1.x + mx * mx * s0) / denom, 0.f);
        float vy = fmaxf((s2.y - 2.f * my * s1.y + my * my * s0) / denom, 0.f);
        float a = sbu - bi[o] * (sfa - s0);

        float2* mu2  = reinterpret_cast<float2*>(g_mu  + (size_t)bid * OUTD);
        float2* i2v2 = reinterpret_cast<float2*>(g_i2v + (size_t)bid * OUTD);
        mu2[lane]  = make_float2(mx, my);
        i2v2[lane] = make_float2(1.f / (2.f * vx + EPSV), 1.f / (2.f * vy + EPSV));

        float lv = logf(vx + EPSV) + logf(vy + EPSV);
        #pragma unroll
        for (int off = 16; off; off >>= 1) lv += __shfl_down_sync(0xffffffffu, lv, off);
        if (lane == 0) {
            float lsig = (a > 0.f) ? -log1pf(expf(-a)) : a - log1pf(expf(a));
            g_C[bid] = lsig - 1.f - 0.5f * 3.14159265358979323846f - 0.5f * lv;
        }

        if (write_out) {
            if (lane == 0) out[n * NO + o] = a;                          // a_out (N, NO)
            float2* om = reinterpret_cast<float2*>(out + NB * NO + ((size_t)n * NO + o) * OUTD);
            om[lane] = make_float2(mx, my);                               // mu_out (N, NO, OUT)
        }
    }
}

// ---------------- kernel 4: routing (R update) -------------------------------
// grid = L*NB (bid = l*64 + n), block = 256 (8 warps). float2 loads.
__global__ __launch_bounds__(256) void route_kernel()
{
    const int bid = blockIdx.x;
    const int l = bid >> 6, n = bid & 63;
    const int w = threadIdx.x >> 5, lane = threadIdx.x & 31;

    __shared__ float logit[NO];
    const float2* V2 = reinterpret_cast<const float2*>(g_V);
    const float2* M2 = reinterpret_cast<const float2*>(g_mu);
    const float2* I2 = reinterpret_cast<const float2*>(g_i2v);

    float2 v[4], m[4], iv[4];
    #pragma unroll
    for (int s = 0; s < 4; s++) {
        int o = s * 8 + w;
        v[s]  = V2[(((size_t)l * NO + o) * NB + n) * 32 + lane];
        m[s]  = M2[((size_t)o * NB + n) * 32 + lane];
        iv[s] = I2[((size_t)o * NB + n) * 32 + lane];
    }
    #pragma unroll
    for (int s = 0; s < 4; s++) {
        int o = s * 8 + w;
        float dx = v[s].x - m[s].x, dy = v[s].y - m[s].y;
        float acc = dx * dx * iv[s].x + dy * dy * iv[s].y;
        #pragma unroll
        for (int off = 16; off; off >>= 1) acc += __shfl_down_sync(0xffffffffu, acc, off);
        if (lane == 0) logit[o] = g_C[o * NB + n] - acc;
    }
    __syncthreads();

    if (w == 0) {
        float val = logit[lane];
        float mx = val;
        #pragma unroll
        for (int off = 16; off; off >>= 1) mx = fmaxf(mx, __shfl_xor_sync(0xffffffffu, mx, off));
        float e = expf(val - mx);
        float ss = e;
        #pragma unroll
        for (int off = 16; off; off >>= 1) ss += __shfl_xor_sync(0xffffffffu, ss, off);
        g_R[((size_t)lane * NB + n) * L + l] = e / ss;   // R layout (o, n, l)
    }
}

// ---------------- launch ------------------------------------------------------
extern "C" void kernel_launch(void* const* d_in, const int* in_sizes, int n_in,
                              void* d_out, int out_size)
{
    const float* x      = (const float*)d_in[0];
    const float* Wscore = (const float*)d_in[1];
    const float* Bscore = (const float*)d_in[2];
    const float* Wcap   = (const float*)d_in[3];
    const float* Bcap   = (const float*)d_in[4];
    const float* Wvote  = (const float*)d_in[5];
    const float* Bvote  = (const float*)d_in[6];
    const float* bu     = (const float*)d_in[7];
    const float* bi     = (const float*)d_in[8];
    float* out = (float*)d_out;

    front_kernel<<<L, 256>>>(x, Wscore, Bscore, Wcap, Bcap);
    vote_kernel<<<L * NO, 256>>>(Wvote, Bvote);

    // iters = 3: E(uniform), R, E, R, E(write_out)
    em_kernel<<<NO * NB, 64>>>(bu, bi, 1, 0, out);
    route_kernel<<<L * NB, 256>>>();
    em_kernel<<<NO * NB, 64>>>(bu, bi, 0, 0, out);
    route_kernel<<<L * NB, 256>>>();
    em_kernel<<<NO * NB, 64>>>(bu, bi, 0, 1, out);
}